// round 4
// baseline (speedup 1.0000x reference)
#include <cuda_runtime.h>
#include <math.h>

#define TPB   256
#define NWARP 8
#define TCC   16   // input channels per gather tile

typedef unsigned long long ull;

// ---------------- transposed-weight scratch (prep kernels fill these) -------
// Layout: Wt[(c*3 + k)*COUT + o] = W[(o*CIN + c)*3 + k]
__device__ __align__(16) float g_Wt1[128 * 3 * 256];   // layer1: CIN=128, COUT=256
__device__ __align__(16) float g_Wt2[256 * 3 * 128];   // layer2
__device__ __align__(16) float g_Wt3[128 * 3 * 64];    // layer3

// ---------------- f32x2 helpers (sm_100+ packed fp32) -----------------------
__device__ __forceinline__ ull fma2(ull a, ull b, ull c) {
    ull d;
    asm("fma.rn.f32x2 %0, %1, %2, %3;" : "=l"(d) : "l"(a), "l"(b), "l"(c));
    return d;
}
__device__ __forceinline__ ull dup2(float x) {
    ull d;
    asm("mov.b64 %0, {%1, %1};" : "=l"(d) : "f"(x));
    return d;
}
__device__ __forceinline__ float2 unpack2(ull v) {
    float2 r;
    asm("mov.b64 {%0, %1}, %2;" : "=f"(r.x), "=f"(r.y) : "l"(v));
    return r;
}
__device__ __forceinline__ float wredsum(float v) {
#pragma unroll
    for (int o = 16; o; o >>= 1) v += __shfl_xor_sync(0xffffffffu, v, o);
    return v;
}
__device__ __forceinline__ float wredmax(float v) {
#pragma unroll
    for (int o = 16; o; o >>= 1) v = fmaxf(v, __shfl_xor_sync(0xffffffffu, v, o));
    return v;
}

// ---------------- weight transpose prep ------------------------------------
template <int CIN, int COUT>
__device__ __forceinline__ void prep_body(const float* __restrict__ W, float* __restrict__ Wt) {
    int i = blockIdx.x * blockDim.x + threadIdx.x;
    if (i < CIN * 3 * COUT) {
        int o  = i % COUT;
        int ck = i / COUT;   // = c*3 + k
        int k  = ck % 3;
        int c  = ck / 3;
        Wt[i] = W[(o * CIN + c) * 3 + k];
    }
}
__global__ void prep1(const float* __restrict__ W) { prep_body<128, 256>(W, g_Wt1); }
__global__ void prep2(const float* __restrict__ W) { prep_body<256, 128>(W, g_Wt2); }
__global__ void prep3(const float* __restrict__ W) { prep_body<128, 64 >(W, g_Wt3); }

// ---------------- gather one c-tile into G ----------------------------------
// G[(c_local*3 + k)*128 + m] = sIn[(cb + c_local)*128 + IDX[3m + k]],  m<127
// column 127 is zero padding so float4 loads at m0=124 are harmless.
__device__ __forceinline__ void gather_tile(const float* __restrict__ sIn,
                                            float* __restrict__ G,
                                            const int* __restrict__ IDX,
                                            int cb, int tid) {
    for (int e = tid; e < 3 * TCC * 127; e += TPB) {
        int jl = e / 127;
        int m  = e - jl * 127;
        int c  = jl / 3;
        int k  = jl - c * 3;
        G[jl * 128 + m] = sIn[(cb + c) * 128 + IDX[3 * m + k]];
    }
    for (int jl = tid; jl < 3 * TCC; jl += TPB) G[jl * 128 + 127] = 0.f;
}

// ---------------- GEMM accumulate over one tile ------------------------------
// acc[j][mi] packs output pair (o = Obase+2j, Obase+2j+1) at m = 4*lane + mi
template <int COUT, int OW>
__device__ __forceinline__ void accum_tile(const float* __restrict__ G,
                                           const float* __restrict__ Wt,
                                           int cb, int Obase, int m0,
                                           ull (&acc)[OW / 2][4]) {
#pragma unroll 4
    for (int cl = 0; cl < TCC; cl++) {
        const float* gr = G + cl * 384 + m0;
        float4 g0 = *(const float4*)(gr);
        float4 g1 = *(const float4*)(gr + 128);
        float4 g2 = *(const float4*)(gr + 256);
        ull gd[3][4];
        gd[0][0] = dup2(g0.x); gd[0][1] = dup2(g0.y); gd[0][2] = dup2(g0.z); gd[0][3] = dup2(g0.w);
        gd[1][0] = dup2(g1.x); gd[1][1] = dup2(g1.y); gd[1][2] = dup2(g1.z); gd[1][3] = dup2(g1.w);
        gd[2][0] = dup2(g2.x); gd[2][1] = dup2(g2.y); gd[2][2] = dup2(g2.z); gd[2][3] = dup2(g2.w);
        const float* wb = Wt + (size_t)((cb + cl) * 3) * COUT + Obase;
#pragma unroll
        for (int k = 0; k < 3; k++) {
            const ulonglong2* wp = (const ulonglong2*)(wb + k * COUT);
#pragma unroll
            for (int jj = 0; jj < OW / 4; jj++) {
                ulonglong2 wv = wp[jj];   // packs {W[o],W[o+1]} | {W[o+2],W[o+3]}
#pragma unroll
                for (int mi = 0; mi < 4; mi++) {
                    acc[2 * jj    ][mi] = fma2(wv.x, gd[k][mi], acc[2 * jj    ][mi]);
                    acc[2 * jj + 1][mi] = fma2(wv.y, gd[k][mi], acc[2 * jj + 1][mi]);
                }
            }
        }
    }
}

// ---------------- conv + store + LayerNorm (+leaky) --------------------------
template <int CIN, int COUT, bool LEAKY>
__device__ __forceinline__ void conv_store(
    const float* __restrict__ sIn, float* __restrict__ sOut,
    const float* __restrict__ Wt, const float* __restrict__ bias,
    float* __restrict__ G, const int* __restrict__ IDX,
    float* __restrict__ RED, float* __restrict__ STAT,
    int tid, int w, int lane) {
    constexpr int OWR = COUT / NWARP;
    constexpr int OW  = (OWR > 16) ? 16 : OWR;   // o's per warp per sweep
    constexpr int NSW = OWR / OW;                // sweeps (2 for COUT=256)
    const int m0 = lane * 4;
    float ls1 = 0.f, ls2 = 0.f;

#pragma unroll 1
    for (int sw = 0; sw < NSW; sw++) {
        const int Obase = (sw * NWARP + w) * OW;
        ull acc[OW / 2][4];
#pragma unroll
        for (int j = 0; j < OW / 2; j++)
#pragma unroll
            for (int mi = 0; mi < 4; mi++) acc[j][mi] = 0ull;

#pragma unroll 1
        for (int cb = 0; cb < CIN; cb += TCC) {
            __syncthreads();                 // previous tile fully consumed
            gather_tile(sIn, G, IDX, cb, tid);
            __syncthreads();
            accum_tile<COUT, OW>(G, Wt, cb, Obase, m0, acc);
        }

        // store + running sum/sumsq (zero column contributes 0 pre-LN)
#pragma unroll
        for (int j = 0; j < OW / 2; j++) {
            int o0 = Obase + 2 * j;
            float bb0 = bias[o0], bb1 = bias[o0 + 1];
#pragma unroll
            for (int mi = 0; mi < 4; mi++) {
                int m = m0 + mi;
                if (m < 127) {
                    float2 v = unpack2(acc[j][mi]);
                    float x0 = v.x + bb0, x1 = v.y + bb1;
                    sOut[o0 * 128 + m + 1]       = x0;
                    sOut[(o0 + 1) * 128 + m + 1] = x1;
                    ls1 += x0 + x1;
                    ls2 += x0 * x0 + x1 * x1;
                }
            }
        }
    }
    // zero-pad column 0 (prepended zero slot, pre-LN value is exactly 0)
    for (int o = tid; o < COUT; o += TPB) sOut[o * 128] = 0.f;

    // block reduction -> mean, 1/(std+eps)  (unbiased, n includes zero column)
    float r1 = wredsum(ls1), r2 = wredsum(ls2);
    if (lane == 0) { RED[w] = r1; RED[NWARP + w] = r2; }
    __syncthreads();
    if (tid == 0) {
        float s1 = 0.f, s2 = 0.f;
#pragma unroll
        for (int i = 0; i < NWARP; i++) { s1 += RED[i]; s2 += RED[NWARP + i]; }
        const float n = (float)(COUT * 128);
        float mean = s1 / n;
        float var  = fmaxf((s2 - s1 * mean) / (n - 1.0f), 0.f);
        STAT[0] = mean;
        STAT[1] = 1.0f / (sqrtf(var) + 1e-5f);
    }
    __syncthreads();
    float mean = STAT[0], inv = STAT[1];
    float4* ov = (float4*)sOut;
    for (int i = tid; i < COUT * 32; i += TPB) {
        float4 v = ov[i];
        v.x = (v.x - mean) * inv; v.y = (v.y - mean) * inv;
        v.z = (v.z - mean) * inv; v.w = (v.w - mean) * inv;
        if (LEAKY) {
            v.x = v.x > 0.f ? v.x : 0.01f * v.x;
            v.y = v.y > 0.f ? v.y : 0.01f * v.y;
            v.z = v.z > 0.f ? v.z : 0.01f * v.z;
            v.w = v.w > 0.f ? v.w : 0.01f * v.w;
        }
        ov[i] = v;
    }
    __syncthreads();
}

// ---------------- layer3: conv + LN stats + channel max, no store ------------
// LN is monotone => pooled_ln[c] = (max(0, max_m conv[c][m]) - mean) * inv
template <int CIN, int COUT>
__device__ __forceinline__ void conv_pool(
    const float* __restrict__ sIn,
    const float* __restrict__ Wt, const float* __restrict__ bias,
    float* __restrict__ G, const int* __restrict__ IDX,
    float* __restrict__ RED, float* __restrict__ POOL, float* __restrict__ STAT,
    int tid, int w, int lane) {
    constexpr int OW = COUT / NWARP;   // 8
    const int m0 = lane * 4;
    const int Obase = w * OW;
    ull acc[OW / 2][4];
#pragma unroll
    for (int j = 0; j < OW / 2; j++)
#pragma unroll
        for (int mi = 0; mi < 4; mi++) acc[j][mi] = 0ull;

#pragma unroll 1
    for (int cb = 0; cb < CIN; cb += TCC) {
        __syncthreads();
        gather_tile(sIn, G, IDX, cb, tid);
        __syncthreads();
        accum_tile<COUT, OW>(G, Wt, cb, Obase, m0, acc);
    }

    float ls1 = 0.f, ls2 = 0.f;
    float omax[OW];
#pragma unroll
    for (int j = 0; j < OW / 2; j++) {
        int o0 = Obase + 2 * j;
        float bb0 = bias[o0], bb1 = bias[o0 + 1];
        float t0 = -3.4e38f, t1 = -3.4e38f;
#pragma unroll
        for (int mi = 0; mi < 4; mi++) {
            if (m0 + mi < 127) {
                float2 v = unpack2(acc[j][mi]);
                float x0 = v.x + bb0, x1 = v.y + bb1;
                ls1 += x0 + x1;
                ls2 += x0 * x0 + x1 * x1;
                t0 = fmaxf(t0, x0);
                t1 = fmaxf(t1, x1);
            }
        }
        omax[2 * j] = t0; omax[2 * j + 1] = t1;
    }
#pragma unroll
    for (int j = 0; j < OW; j++) {
        float mx = wredmax(omax[j]);
        if (lane == 0) POOL[Obase + j] = fmaxf(mx, 0.f);  // zero column joins max
    }
    float r1 = wredsum(ls1), r2 = wredsum(ls2);
    if (lane == 0) { RED[w] = r1; RED[NWARP + w] = r2; }
    __syncthreads();
    if (tid == 0) {
        float s1 = 0.f, s2 = 0.f;
#pragma unroll
        for (int i = 0; i < NWARP; i++) { s1 += RED[i]; s2 += RED[NWARP + i]; }
        const float n = (float)(COUT * 128);
        float mean = s1 / n;
        float var  = fmaxf((s2 - s1 * mean) / (n - 1.0f), 0.f);
        STAT[0] = mean;
        STAT[1] = 1.0f / (sqrtf(var) + 1e-5f);
    }
    __syncthreads();
}

// ---------------- fused per-tree kernel --------------------------------------
#define SMEM_FLOATS (32768 + 16384 + 3 * TCC * 128 + 384 + 2 * NWARP + 64 + 2)
#define SMEM_BYTES  (SMEM_FLOATS * 4)

__global__ void __launch_bounds__(TPB, 1) bao_kernel(
    const float* __restrict__ trees, const int* __restrict__ indexes,
    const float* __restrict__ b1, const float* __restrict__ b2,
    const float* __restrict__ b3,
    const float* __restrict__ W4, const float* __restrict__ b4,
    const float* __restrict__ W5, const float* __restrict__ b5,
    float* __restrict__ out) {
    extern __shared__ float sm[];
    float* S1   = sm;                              // 256x128 (L1 out / L2 in)
    float* S0   = sm + 32768;                      // 128x128 (trees / L2 out / L3 in)
    float* G    = sm + 49152;                      // 48x128 gather tile
    int*   IDX  = (int*)(sm + 49152 + 3 * TCC * 128);
    float* RED  = (float*)(IDX + 384);
    float* POOL = RED + 2 * NWARP;
    float* STAT = POOL + 64;

    const int tid = threadIdx.x, w = tid >> 5, lane = tid & 31;
    const int b = blockIdx.x;

    // stage tree + indexes into smem
    const float4* tin = (const float4*)(trees + (size_t)b * 16384);
    float4* s0v = (float4*)S0;
    for (int i = tid; i < 4096; i += TPB) s0v[i] = tin[i];
    const int* ip = indexes + (size_t)b * 381;
    for (int i = tid; i < 381; i += TPB) IDX[i] = ip[i];
    __syncthreads();

    conv_store<128, 256, true>(S0, S1, g_Wt1, b1, G, IDX, RED, STAT, tid, w, lane);
    conv_store<256, 128, true>(S1, S0, g_Wt2, b2, G, IDX, RED, STAT, tid, w, lane);
    conv_pool <128, 64>(S0, g_Wt3, b3, G, IDX, RED, POOL, STAT, tid, w, lane);

    // head on warp 0: h = leaky(pooled_ln @ W4^T + b4); out = h @ W5^T + b5
    if (w == 0) {
        float mean = STAT[0], inv = STAT[1];
        float hv = b4[lane];
#pragma unroll 8
        for (int c = 0; c < 64; c++)
            hv += (POOL[c] - mean) * inv * W4[lane * 64 + c];
        hv = hv > 0.f ? hv : 0.01f * hv;
        float val = wredsum(hv * W5[lane]);
        if (lane == 0) out[b] = val + b5[0];
    }
}

extern "C" void kernel_launch(void* const* d_in, const int* in_sizes, int n_in,
                              void* d_out, int out_size) {
    const float* trees = nullptr; const int* indexes = nullptr;
    const float *W1 = nullptr, *b1 = nullptr, *W2 = nullptr, *b2 = nullptr;
    const float *W3 = nullptr, *b3 = nullptr, *W4 = nullptr, *b4 = nullptr;
    const float *W5 = nullptr, *b5 = nullptr;

    for (int i = 0; i < n_in; i++) {
        int s = in_sizes[i];
        const void* p = d_in[i];
        switch (s) {
            case 33554432: trees   = (const float*)p; break;
            case 780288:   indexes = (const int*)p;   break;
            case 98304:    if (!W1) W1 = (const float*)p; else W2 = (const float*)p; break;
            case 256:      b1 = (const float*)p; break;
            case 128:      b2 = (const float*)p; break;
            case 24576:    W3 = (const float*)p; break;
            case 64:       b3 = (const float*)p; break;
            case 2048:     W4 = (const float*)p; break;
            case 32:       if (!b4) b4 = (const float*)p; else W5 = (const float*)p; break;
            case 1:        b5 = (const float*)p; break;
            default: break;
        }
    }

    prep1<<<(128 * 3 * 256 + 255) / 256, 256>>>(W1);
    prep2<<<(256 * 3 * 128 + 255) / 256, 256>>>(W2);
    prep3<<<(128 * 3 * 64  + 255) / 256, 256>>>(W3);

    cudaFuncSetAttribute(bao_kernel, cudaFuncAttributeMaxDynamicSharedMemorySize, SMEM_BYTES);
    bao_kernel<<<2048, TPB, SMEM_BYTES>>>(trees, indexes, b1, b2, b3, W4, b4, W5, b5,
                                          (float*)d_out);
}

// round 5
// speedup vs baseline: 1.0796x; 1.0796x over previous
#include <cuda_runtime.h>
#include <math.h>

#define TPB   256
#define NWARP 8
#define TCC   8    // input channels per gather tile (double-buffered)

typedef unsigned long long ull;

// ---------------- transposed-weight scratch (prep kernels fill these) -------
// Layout: Wt[(c*3 + k)*COUT + o] = W[(o*CIN + c)*3 + k]
__device__ __align__(16) float g_Wt1[128 * 3 * 256];   // layer1: CIN=128, COUT=256
__device__ __align__(16) float g_Wt2[256 * 3 * 128];   // layer2
__device__ __align__(16) float g_Wt3[128 * 3 * 64];    // layer3

// ---------------- f32x2 helpers (sm_100+ packed fp32) -----------------------
__device__ __forceinline__ ull fma2(ull a, ull b, ull c) {
    ull d;
    asm("fma.rn.f32x2 %0, %1, %2, %3;" : "=l"(d) : "l"(a), "l"(b), "l"(c));
    return d;
}
__device__ __forceinline__ ull dup2(float x) {
    ull d;
    asm("mov.b64 %0, {%1, %1};" : "=l"(d) : "f"(x));
    return d;
}
__device__ __forceinline__ float2 unpack2(ull v) {
    float2 r;
    asm("mov.b64 {%0, %1}, %2;" : "=f"(r.x), "=f"(r.y) : "l"(v));
    return r;
}
__device__ __forceinline__ float wredsum(float v) {
#pragma unroll
    for (int o = 16; o; o >>= 1) v += __shfl_xor_sync(0xffffffffu, v, o);
    return v;
}
__device__ __forceinline__ float wredmax(float v) {
#pragma unroll
    for (int o = 16; o; o >>= 1) v = fmaxf(v, __shfl_xor_sync(0xffffffffu, v, o));
    return v;
}

// ---------------- weight transpose prep ------------------------------------
template <int CIN, int COUT>
__device__ __forceinline__ void prep_body(const float* __restrict__ W, float* __restrict__ Wt) {
    int i = blockIdx.x * blockDim.x + threadIdx.x;
    if (i < CIN * 3 * COUT) {
        int o  = i % COUT;
        int ck = i / COUT;   // = c*3 + k
        int k  = ck % 3;
        int c  = ck / 3;
        Wt[i] = W[(o * CIN + c) * 3 + k];
    }
}
__global__ void prep1(const float* __restrict__ W) { prep_body<128, 256>(W, g_Wt1); }
__global__ void prep2(const float* __restrict__ W) { prep_body<256, 128>(W, g_Wt2); }
__global__ void prep3(const float* __restrict__ W) { prep_body<128, 64 >(W, g_Wt3); }

// ---------------- gather one c-tile into G (LN+leaky folded in) -------------
// G[(c_local*3 + k)*128 + m] = xform(sIn[(cb + c_local)*128 + IDX[3m + k]]), m<127
// column 127 is zero padding so float4 loads at m0=124 are harmless.
template <bool XF>
__device__ __forceinline__ void gather_tile(const float* __restrict__ sIn,
                                            float* __restrict__ G,
                                            const int* __restrict__ IDX,
                                            int cb, int tid, float mean, float inv) {
#pragma unroll
    for (int r = 0; r < (3 * TCC * 127 + TPB - 1) / TPB; r++) {
        int e = tid + r * TPB;
        if (e < 3 * TCC * 127) {
            int jl = e / 127;
            int m  = e - jl * 127;
            int c  = jl / 3;
            int k  = jl - c * 3;
            float v = sIn[(cb + c) * 128 + IDX[3 * m + k]];
            if (XF) { v = (v - mean) * inv; v = fmaxf(v, 0.01f * v); }  // LN + leaky
            G[jl * 128 + m] = v;
        }
    }
    if (tid < 3 * TCC) G[tid * 128 + 127] = 0.f;
}

// ---------------- GEMM accumulate over one tile ------------------------------
// acc[j][mi] packs output pair (o = Obase+2j, Obase+2j+1) at m = 4*lane + mi
template <int COUT, int OW>
__device__ __forceinline__ void accum_tile(const float* __restrict__ G,
                                           const float* __restrict__ Wt,
                                           int cb, int Obase, int m0,
                                           ull (&acc)[OW / 2][4]) {
#pragma unroll 4
    for (int cl = 0; cl < TCC; cl++) {
        const float* gr = G + cl * 384 + m0;
        float4 g0 = *(const float4*)(gr);
        float4 g1 = *(const float4*)(gr + 128);
        float4 g2 = *(const float4*)(gr + 256);
        ull gd[3][4];
        gd[0][0] = dup2(g0.x); gd[0][1] = dup2(g0.y); gd[0][2] = dup2(g0.z); gd[0][3] = dup2(g0.w);
        gd[1][0] = dup2(g1.x); gd[1][1] = dup2(g1.y); gd[1][2] = dup2(g1.z); gd[1][3] = dup2(g1.w);
        gd[2][0] = dup2(g2.x); gd[2][1] = dup2(g2.y); gd[2][2] = dup2(g2.z); gd[2][3] = dup2(g2.w);
        const float* wb = Wt + (size_t)((cb + cl) * 3) * COUT + Obase;
#pragma unroll
        for (int k = 0; k < 3; k++) {
            const ulonglong2* wp = (const ulonglong2*)(wb + k * COUT);
#pragma unroll
            for (int jj = 0; jj < OW / 4; jj++) {
                ulonglong2 wv = wp[jj];   // packs {W[o],W[o+1]} | {W[o+2],W[o+3]}
#pragma unroll
                for (int mi = 0; mi < 4; mi++) {
                    acc[2 * jj    ][mi] = fma2(wv.x, gd[k][mi], acc[2 * jj    ][mi]);
                    acc[2 * jj + 1][mi] = fma2(wv.y, gd[k][mi], acc[2 * jj + 1][mi]);
                }
            }
        }
    }
}

// ---------------- pipelined sweep: gather tile t+1 while computing tile t ----
template <int CIN, int COUT, int OW, bool XF>
__device__ __forceinline__ void conv_sweep(const float* __restrict__ sIn,
                                           const float* __restrict__ Wt,
                                           float* __restrict__ G0, float* __restrict__ G1,
                                           const int* __restrict__ IDX,
                                           int Obase, int m0, int tid,
                                           float xm, float xi,
                                           ull (&acc)[OW / 2][4]) {
    constexpr int NT = CIN / TCC;
    gather_tile<XF>(sIn, G0, IDX, 0, tid, xm, xi);
#pragma unroll 1
    for (int t = 0; t < NT; t++) {
        __syncthreads();   // gather of buf[t&1] done; prior reads of buf[(t+1)&1] done
        if (t + 1 < NT)
            gather_tile<XF>(sIn, (t & 1) ? G0 : G1, IDX, (t + 1) * TCC, tid, xm, xi);
        accum_tile<COUT, OW>((t & 1) ? G1 : G0, Wt, t * TCC, Obase, m0, acc);
    }
    __syncthreads();   // all reads of G0/G1 done before any later gather reuses them
}

// ---------------- conv + store + LN stats (no normalize pass) ----------------
// Stores PRE-LN values in sOut; writes mean/inv to STAT. The next layer applies
// the affine LN + leaky on gather.
template <int CIN, int COUT, bool XF>
__device__ __forceinline__ void conv_store(
    const float* __restrict__ sIn, float* __restrict__ sOut,
    const float* __restrict__ Wt, const float* __restrict__ bias,
    float* __restrict__ G0, float* __restrict__ G1, const int* __restrict__ IDX,
    float* __restrict__ RED, float* __restrict__ STAT,
    int tid, int w, int lane, float xm, float xi) {
    constexpr int OWR = COUT / NWARP;
    constexpr int OW  = (OWR > 16) ? 16 : OWR;   // o's per warp per sweep
    constexpr int NSW = OWR / OW;                // sweeps (2 for COUT=256)
    const int m0 = lane * 4;
    float ls1 = 0.f, ls2 = 0.f;

#pragma unroll 1
    for (int sw = 0; sw < NSW; sw++) {
        const int Obase = (sw * NWARP + w) * OW;
        ull acc[OW / 2][4];
#pragma unroll
        for (int j = 0; j < OW / 2; j++)
#pragma unroll
            for (int mi = 0; mi < 4; mi++) acc[j][mi] = 0ull;

        conv_sweep<CIN, COUT, OW, XF>(sIn, Wt, G0, G1, IDX, Obase, m0, tid, xm, xi, acc);

        // store + running sum/sumsq (zero column contributes 0 pre-LN)
#pragma unroll
        for (int j = 0; j < OW / 2; j++) {
            int o0 = Obase + 2 * j;
            float bb0 = bias[o0], bb1 = bias[o0 + 1];
#pragma unroll
            for (int mi = 0; mi < 4; mi++) {
                int m = m0 + mi;
                if (m < 127) {
                    float2 v = unpack2(acc[j][mi]);
                    float x0 = v.x + bb0, x1 = v.y + bb1;
                    sOut[o0 * 128 + m + 1]       = x0;
                    sOut[(o0 + 1) * 128 + m + 1] = x1;
                    ls1 += x0 + x1;
                    ls2 += x0 * x0 + x1 * x1;
                }
            }
        }
    }
    // zero-pad column 0 (prepended zero slot, pre-LN value is exactly 0)
    for (int o = tid; o < COUT; o += TPB) sOut[o * 128] = 0.f;

    // block reduction -> mean, 1/(std+eps)  (unbiased, n includes zero column)
    float r1 = wredsum(ls1), r2 = wredsum(ls2);
    if (lane == 0) { RED[w] = r1; RED[NWARP + w] = r2; }
    __syncthreads();          // also orders sOut stores before next layer's gather
    if (tid == 0) {
        float s1 = 0.f, s2 = 0.f;
#pragma unroll
        for (int i = 0; i < NWARP; i++) { s1 += RED[i]; s2 += RED[NWARP + i]; }
        const float n = (float)(COUT * 128);
        float mean = s1 / n;
        float var  = fmaxf((s2 - s1 * mean) / (n - 1.0f), 0.f);
        STAT[0] = mean;
        STAT[1] = 1.0f / (sqrtf(var) + 1e-5f);
    }
    __syncthreads();
}

// ---------------- layer3: conv + LN stats + channel max, no store ------------
// LN is monotone => pooled_ln[c] = (max(0, max_m conv[c][m]) - mean) * inv
template <int CIN, int COUT, bool XF>
__device__ __forceinline__ void conv_pool(
    const float* __restrict__ sIn,
    const float* __restrict__ Wt, const float* __restrict__ bias,
    float* __restrict__ G0, float* __restrict__ G1, const int* __restrict__ IDX,
    float* __restrict__ RED, float* __restrict__ POOL, float* __restrict__ STAT,
    int tid, int w, int lane, float xm, float xi) {
    constexpr int OW = COUT / NWARP;   // 8
    const int m0 = lane * 4;
    const int Obase = w * OW;
    ull acc[OW / 2][4];
#pragma unroll
    for (int j = 0; j < OW / 2; j++)
#pragma unroll
        for (int mi = 0; mi < 4; mi++) acc[j][mi] = 0ull;

    conv_sweep<CIN, COUT, OW, XF>(sIn, Wt, G0, G1, IDX, Obase, m0, tid, xm, xi, acc);

    float ls1 = 0.f, ls2 = 0.f;
    float omax[OW];
#pragma unroll
    for (int j = 0; j < OW / 2; j++) {
        int o0 = Obase + 2 * j;
        float bb0 = bias[o0], bb1 = bias[o0 + 1];
        float t0 = -3.4e38f, t1 = -3.4e38f;
#pragma unroll
        for (int mi = 0; mi < 4; mi++) {
            if (m0 + mi < 127) {
                float2 v = unpack2(acc[j][mi]);
                float x0 = v.x + bb0, x1 = v.y + bb1;
                ls1 += x0 + x1;
                ls2 += x0 * x0 + x1 * x1;
                t0 = fmaxf(t0, x0);
                t1 = fmaxf(t1, x1);
            }
        }
        omax[2 * j] = t0; omax[2 * j + 1] = t1;
    }
#pragma unroll
    for (int j = 0; j < OW; j++) {
        float mx = wredmax(omax[j]);
        if (lane == 0) POOL[Obase + j] = fmaxf(mx, 0.f);  // zero column joins max
    }
    float r1 = wredsum(ls1), r2 = wredsum(ls2);
    if (lane == 0) { RED[w] = r1; RED[NWARP + w] = r2; }
    __syncthreads();
    if (tid == 0) {
        float s1 = 0.f, s2 = 0.f;
#pragma unroll
        for (int i = 0; i < NWARP; i++) { s1 += RED[i]; s2 += RED[NWARP + i]; }
        const float n = (float)(COUT * 128);
        float mean = s1 / n;
        float var  = fmaxf((s2 - s1 * mean) / (n - 1.0f), 0.f);
        STAT[0] = mean;
        STAT[1] = 1.0f / (sqrtf(var) + 1e-5f);
    }
    __syncthreads();
}

// ---------------- fused per-tree kernel --------------------------------------
#define SMEM_FLOATS (32768 + 16384 + 2 * (3 * TCC * 128) + 384 + 2 * NWARP + 64 + 2)
#define SMEM_BYTES  (SMEM_FLOATS * 4)

__global__ void __launch_bounds__(TPB, 1) bao_kernel(
    const float* __restrict__ trees, const int* __restrict__ indexes,
    const float* __restrict__ b1, const float* __restrict__ b2,
    const float* __restrict__ b3,
    const float* __restrict__ W4, const float* __restrict__ b4,
    const float* __restrict__ W5, const float* __restrict__ b5,
    float* __restrict__ out) {
    extern __shared__ float sm[];
    float* S1   = sm;                              // 256x128 (L1 out / L2 in), pre-LN
    float* S0   = sm + 32768;                      // 128x128 (trees / L2 out / L3 in)
    float* G0   = sm + 49152;                      // gather tile buf 0 (24x128)
    float* G1   = G0 + 3 * TCC * 128;              // gather tile buf 1
    int*   IDX  = (int*)(G1 + 3 * TCC * 128);
    float* RED  = (float*)(IDX + 384);
    float* POOL = RED + 2 * NWARP;
    float* STAT = POOL + 64;

    const int tid = threadIdx.x, w = tid >> 5, lane = tid & 31;
    const int b = blockIdx.x;

    // stage tree + indexes into smem
    const float4* tin = (const float4*)(trees + (size_t)b * 16384);
    float4* s0v = (float4*)S0;
    for (int i = tid; i < 4096; i += TPB) s0v[i] = tin[i];
    const int* ip = indexes + (size_t)b * 381;
    for (int i = tid; i < 381; i += TPB) IDX[i] = ip[i];
    __syncthreads();

    conv_store<128, 256, false>(S0, S1, g_Wt1, b1, G0, G1, IDX, RED, STAT,
                                tid, w, lane, 0.f, 1.f);
    float m1 = STAT[0], i1 = STAT[1];
    conv_store<256, 128, true >(S1, S0, g_Wt2, b2, G0, G1, IDX, RED, STAT,
                                tid, w, lane, m1, i1);
    float m2 = STAT[0], i2 = STAT[1];
    conv_pool <128, 64, true>(S0, g_Wt3, b3, G0, G1, IDX, RED, POOL, STAT,
                              tid, w, lane, m2, i2);

    // head on warp 0: h = leaky(pooled_ln @ W4^T + b4); out = h @ W5^T + b5
    if (w == 0) {
        float mean = STAT[0], inv = STAT[1];
        float hv = b4[lane];
#pragma unroll 8
        for (int c = 0; c < 64; c++)
            hv += (POOL[c] - mean) * inv * W4[lane * 64 + c];
        hv = hv > 0.f ? hv : 0.01f * hv;
        float val = wredsum(hv * W5[lane]);
        if (lane == 0) out[b] = val + b5[0];
    }
}

extern "C" void kernel_launch(void* const* d_in, const int* in_sizes, int n_in,
                              void* d_out, int out_size) {
    const float* trees = nullptr; const int* indexes = nullptr;
    const float *W1 = nullptr, *b1 = nullptr, *W2 = nullptr, *b2 = nullptr;
    const float *W3 = nullptr, *b3 = nullptr, *W4 = nullptr, *b4 = nullptr;
    const float *W5 = nullptr, *b5 = nullptr;

    for (int i = 0; i < n_in; i++) {
        int s = in_sizes[i];
        const void* p = d_in[i];
        switch (s) {
            case 33554432: trees   = (const float*)p; break;
            case 780288:   indexes = (const int*)p;   break;
            case 98304:    if (!W1) W1 = (const float*)p; else W2 = (const float*)p; break;
            case 256:      b1 = (const float*)p; break;
            case 128:      b2 = (const float*)p; break;
            case 24576:    W3 = (const float*)p; break;
            case 64:       b3 = (const float*)p; break;
            case 2048:     W4 = (const float*)p; break;
            case 32:       if (!b4) b4 = (const float*)p; else W5 = (const float*)p; break;
            case 1:        b5 = (const float*)p; break;
            default: break;
        }
    }

    prep1<<<(128 * 3 * 256 + 255) / 256, 256>>>(W1);
    prep2<<<(256 * 3 * 128 + 255) / 256, 256>>>(W2);
    prep3<<<(128 * 3 * 64  + 255) / 256, 256>>>(W3);

    cudaFuncSetAttribute(bao_kernel, cudaFuncAttributeMaxDynamicSharedMemorySize, SMEM_BYTES);
    bao_kernel<<<2048, TPB, SMEM_BYTES>>>(trees, indexes, b1, b2, b3, W4, b4, W5, b5,
                                          (float*)d_out);
}

// round 7
// speedup vs baseline: 1.1584x; 1.0730x over previous
#include <cuda_runtime.h>
#include <math.h>

#define TPB   512
#define NWARP 16
#define TCC   8    // input channels per gather tile (double-buffered)

typedef unsigned long long ull;

// ---------------- transposed-weight scratch (prep kernels fill these) -------
// Layout: Wt[(c*3 + k)*COUT + o] = W[(o*CIN + c)*3 + k]
__device__ __align__(16) float g_Wt1[128 * 3 * 256];   // layer1: CIN=128, COUT=256
__device__ __align__(16) float g_Wt2[256 * 3 * 128];   // layer2
__device__ __align__(16) float g_Wt3[128 * 3 * 64];    // layer3

// ---------------- f32x2 helpers (sm_100+ packed fp32) -----------------------
__device__ __forceinline__ ull fma2(ull a, ull b, ull c) {
    ull d;
    asm("fma.rn.f32x2 %0, %1, %2, %3;" : "=l"(d) : "l"(a), "l"(b), "l"(c));
    return d;
}
__device__ __forceinline__ ull dup2(float x) {
    ull d;
    asm("mov.b64 %0, {%1, %1};" : "=l"(d) : "f"(x));
    return d;
}
__device__ __forceinline__ float2 unpack2(ull v) {
    float2 r;
    asm("mov.b64 {%0, %1}, %2;" : "=f"(r.x), "=f"(r.y) : "l"(v));
    return r;
}
__device__ __forceinline__ float wredsum(float v) {
#pragma unroll
    for (int o = 16; o; o >>= 1) v += __shfl_xor_sync(0xffffffffu, v, o);
    return v;
}
__device__ __forceinline__ float wredmax(float v) {
#pragma unroll
    for (int o = 16; o; o >>= 1) v = fmaxf(v, __shfl_xor_sync(0xffffffffu, v, o));
    return v;
}

// ---------------- weight transpose prep ------------------------------------
template <int CIN, int COUT>
__device__ __forceinline__ void prep_body(const float* __restrict__ W, float* __restrict__ Wt) {
    int i = blockIdx.x * blockDim.x + threadIdx.x;
    if (i < CIN * 3 * COUT) {
        int o  = i % COUT;
        int ck = i / COUT;   // = c*3 + k
        int k  = ck % 3;
        int c  = ck / 3;
        Wt[i] = W[(o * CIN + c) * 3 + k];
    }
}
__global__ void prep1(const float* __restrict__ W) { prep_body<128, 256>(W, g_Wt1); }
__global__ void prep2(const float* __restrict__ W) { prep_body<256, 128>(W, g_Wt2); }
__global__ void prep3(const float* __restrict__ W) { prep_body<128, 64 >(W, g_Wt3); }

// ---------------- gather one c-tile into G (LN+leaky folded in) -------------
// G[(c_local*3 + k)*128 + m] = xform(sIn[(cb + c_local)*128 + IDX[3m + k]]), m<127
// column 127 is zero padding so float4 loads at m0=124 are harmless.
template <bool XF>
__device__ __forceinline__ void gather_tile(const float* __restrict__ sIn,
                                            float* __restrict__ G,
                                            const int* __restrict__ IDX,
                                            int cb, int tid, float mean, float inv) {
#pragma unroll
    for (int r = 0; r < (3 * TCC * 127 + TPB - 1) / TPB; r++) {
        int e = tid + r * TPB;
        if (e < 3 * TCC * 127) {
            int jl = e / 127;
            int m  = e - jl * 127;
            int c  = jl / 3;
            int k  = jl - c * 3;
            float v = sIn[(cb + c) * 128 + IDX[3 * m + k]];
            if (XF) { v = (v - mean) * inv; v = fmaxf(v, 0.01f * v); }  // LN + leaky
            G[jl * 128 + m] = v;
        }
    }
    if (tid < 3 * TCC) G[tid * 128 + 127] = 0.f;
}

// ---------------- GEMM accumulate over one tile ------------------------------
// acc[j][mi] packs output pair (o = Obase+2j, Obase+2j+1) at m = 4*lane + mi
template <int COUT, int OW>
__device__ __forceinline__ void accum_tile(const float* __restrict__ G,
                                           const float* __restrict__ Wt,
                                           int cb, int Obase, int m0,
                                           ull (&acc)[OW / 2][4]) {
#pragma unroll 4
    for (int cl = 0; cl < TCC; cl++) {
        const float* gr = G + cl * 384 + m0;
        float4 g0 = *(const float4*)(gr);
        float4 g1 = *(const float4*)(gr + 128);
        float4 g2 = *(const float4*)(gr + 256);
        ull gd[3][4];
        gd[0][0] = dup2(g0.x); gd[0][1] = dup2(g0.y); gd[0][2] = dup2(g0.z); gd[0][3] = dup2(g0.w);
        gd[1][0] = dup2(g1.x); gd[1][1] = dup2(g1.y); gd[1][2] = dup2(g1.z); gd[1][3] = dup2(g1.w);
        gd[2][0] = dup2(g2.x); gd[2][1] = dup2(g2.y); gd[2][2] = dup2(g2.z); gd[2][3] = dup2(g2.w);
        const float* wb = Wt + (size_t)((cb + cl) * 3) * COUT + Obase;
#pragma unroll
        for (int k = 0; k < 3; k++) {
            const ulonglong2* wp = (const ulonglong2*)(wb + k * COUT);
#pragma unroll
            for (int jj = 0; jj < OW / 4; jj++) {
                ulonglong2 wv = wp[jj];   // packs {W[o],W[o+1]} | {W[o+2],W[o+3]}
#pragma unroll
                for (int mi = 0; mi < 4; mi++) {
                    acc[2 * jj    ][mi] = fma2(wv.x, gd[k][mi], acc[2 * jj    ][mi]);
                    acc[2 * jj + 1][mi] = fma2(wv.y, gd[k][mi], acc[2 * jj + 1][mi]);
                }
            }
        }
    }
}

// ---------------- pipelined sweep: gather tile t+1 while computing tile t ----
template <int CIN, int COUT, int OW, bool XF>
__device__ __forceinline__ void conv_sweep(const float* __restrict__ sIn,
                                           const float* __restrict__ Wt,
                                           float* __restrict__ G0, float* __restrict__ G1,
                                           const int* __restrict__ IDX,
                                           int Obase, int m0, int tid,
                                           float xm, float xi,
                                           ull (&acc)[OW / 2][4]) {
    constexpr int NT = CIN / TCC;
    gather_tile<XF>(sIn, G0, IDX, 0, tid, xm, xi);
#pragma unroll 1
    for (int t = 0; t < NT; t++) {
        __syncthreads();   // gather of buf[t&1] done; prior reads of buf[(t+1)&1] done
        if (t + 1 < NT)
            gather_tile<XF>(sIn, (t & 1) ? G0 : G1, IDX, (t + 1) * TCC, tid, xm, xi);
        accum_tile<COUT, OW>((t & 1) ? G1 : G0, Wt, t * TCC, Obase, m0, acc);
    }
    __syncthreads();   // all reads of G0/G1 done before any later gather reuses them
}

// ---------------- conv + store + LN stats (no normalize pass) ----------------
// Stores PRE-LN values in sOut; writes mean/inv to STAT. The next layer applies
// the affine LN + leaky on gather.
template <int CIN, int COUT, bool XF>
__device__ __forceinline__ void conv_store(
    const float* __restrict__ sIn, float* __restrict__ sOut,
    const float* __restrict__ Wt, const float* __restrict__ bias,
    float* __restrict__ G0, float* __restrict__ G1, const int* __restrict__ IDX,
    float* __restrict__ RED, float* __restrict__ STAT,
    int tid, int w, int lane, float xm, float xi) {
    constexpr int OWR = COUT / NWARP;
    constexpr int OW  = (OWR > 8) ? 8 : OWR;     // o's per warp per sweep (reg cap)
    constexpr int NSW = OWR / OW;                // sweeps (2 for COUT=256)
    const int m0 = lane * 4;
    float ls1 = 0.f, ls2 = 0.f;

#pragma unroll 1
    for (int sw = 0; sw < NSW; sw++) {
        const int Obase = (sw * NWARP + w) * OW;
        ull acc[OW / 2][4];
#pragma unroll
        for (int j = 0; j < OW / 2; j++)
#pragma unroll
            for (int mi = 0; mi < 4; mi++) acc[j][mi] = 0ull;

        conv_sweep<CIN, COUT, OW, XF>(sIn, Wt, G0, G1, IDX, Obase, m0, tid, xm, xi, acc);

        // store + running sum/sumsq (zero column contributes 0 pre-LN)
#pragma unroll
        for (int j = 0; j < OW / 2; j++) {
            int o0 = Obase + 2 * j;
            float bb0 = bias[o0], bb1 = bias[o0 + 1];
#pragma unroll
            for (int mi = 0; mi < 4; mi++) {
                int m = m0 + mi;
                if (m < 127) {
                    float2 v = unpack2(acc[j][mi]);
                    float x0 = v.x + bb0, x1 = v.y + bb1;
                    sOut[o0 * 128 + m + 1]       = x0;
                    sOut[(o0 + 1) * 128 + m + 1] = x1;
                    ls1 += x0 + x1;
                    ls2 += x0 * x0 + x1 * x1;
                }
            }
        }
    }
    // zero-pad column 0 (prepended zero slot, pre-LN value is exactly 0)
    for (int o = tid; o < COUT; o += TPB) sOut[o * 128] = 0.f;

    // block reduction -> mean, 1/(std+eps)  (unbiased, n includes zero column)
    float r1 = wredsum(ls1), r2 = wredsum(ls2);
    if (lane == 0) { RED[w] = r1; RED[NWARP + w] = r2; }
    __syncthreads();          // also orders sOut stores before next layer's gather
    if (tid == 0) {
        float s1 = 0.f, s2 = 0.f;
#pragma unroll
        for (int i = 0; i < NWARP; i++) { s1 += RED[i]; s2 += RED[NWARP + i]; }
        const float n = (float)(COUT * 128);
        float mean = s1 / n;
        float var  = fmaxf((s2 - s1 * mean) / (n - 1.0f), 0.f);
        STAT[0] = mean;
        STAT[1] = 1.0f / (sqrtf(var) + 1e-5f);
    }
    __syncthreads();
}

// ---------------- layer3: conv + LN stats + channel max, no store ------------
// LN is monotone => pooled_ln[c] = (max(0, max_m conv[c][m]) - mean) * inv
template <int CIN, int COUT, bool XF>
__device__ __forceinline__ void conv_pool(
    const float* __restrict__ sIn,
    const float* __restrict__ Wt, const float* __restrict__ bias,
    float* __restrict__ G0, float* __restrict__ G1, const int* __restrict__ IDX,
    float* __restrict__ RED, float* __restrict__ POOL, float* __restrict__ STAT,
    int tid, int w, int lane, float xm, float xi) {
    constexpr int OW = COUT / NWARP;   // 4
    const int m0 = lane * 4;
    const int Obase = w * OW;
    ull acc[OW / 2][4];
#pragma unroll
    for (int j = 0; j < OW / 2; j++)
#pragma unroll
        for (int mi = 0; mi < 4; mi++) acc[j][mi] = 0ull;

    conv_sweep<CIN, COUT, OW, XF>(sIn, Wt, G0, G1, IDX, Obase, m0, tid, xm, xi, acc);

    float ls1 = 0.f, ls2 = 0.f;
    float omax[OW];
#pragma unroll
    for (int j = 0; j < OW / 2; j++) {
        int o0 = Obase + 2 * j;
        float bb0 = bias[o0], bb1 = bias[o0 + 1];
        float t0 = -3.4e38f, t1 = -3.4e38f;
#pragma unroll
        for (int mi = 0; mi < 4; mi++) {
            if (m0 + mi < 127) {
                float2 v = unpack2(acc[j][mi]);
                float x0 = v.x + bb0, x1 = v.y + bb1;
                ls1 += x0 + x1;
                ls2 += x0 * x0 + x1 * x1;
                t0 = fmaxf(t0, x0);
                t1 = fmaxf(t1, x1);
            }
        }
        omax[2 * j] = t0; omax[2 * j + 1] = t1;
    }
#pragma unroll
    for (int j = 0; j < OW; j++) {
        float mx = wredmax(omax[j]);
        if (lane == 0) POOL[Obase + j] = fmaxf(mx, 0.f);  // zero column joins max
    }
    float r1 = wredsum(ls1), r2 = wredsum(ls2);
    if (lane == 0) { RED[w] = r1; RED[NWARP + w] = r2; }
    __syncthreads();
    if (tid == 0) {
        float s1 = 0.f, s2 = 0.f;
#pragma unroll
        for (int i = 0; i < NWARP; i++) { s1 += RED[i]; s2 += RED[NWARP + i]; }
        const float n = (float)(COUT * 128);
        float mean = s1 / n;
        float var  = fmaxf((s2 - s1 * mean) / (n - 1.0f), 0.f);
        STAT[0] = mean;
        STAT[1] = 1.0f / (sqrtf(var) + 1e-5f);
    }
    __syncthreads();
}

// ---------------- fused per-tree kernel --------------------------------------
#define SMEM_FLOATS (32768 + 16384 + 2 * (3 * TCC * 128) + 384 + 2 * NWARP + 64 + 2)
#define SMEM_BYTES  (SMEM_FLOATS * 4)

__global__ void __launch_bounds__(TPB, 1) bao_kernel(
    const float* __restrict__ trees, const int* __restrict__ indexes,
    const float* __restrict__ b1, const float* __restrict__ b2,
    const float* __restrict__ b3,
    const float* __restrict__ W4, const float* __restrict__ b4,
    const float* __restrict__ W5, const float* __restrict__ b5,
    float* __restrict__ out) {
    extern __shared__ float sm[];
    float* S1   = sm;                              // 256x128 (L1 out / L2 in), pre-LN
    float* S0   = sm + 32768;                      // 128x128 (trees / L2 out / L3 in)
    float* G0   = sm + 49152;                      // gather tile buf 0 (24x128)
    float* G1   = G0 + 3 * TCC * 128;              // gather tile buf 1
    int*   IDX  = (int*)(G1 + 3 * TCC * 128);
    float* RED  = (float*)(IDX + 384);
    float* POOL = RED + 2 * NWARP;
    float* STAT = POOL + 64;

    const int tid = threadIdx.x, w = tid >> 5, lane = tid & 31;
    const int b = blockIdx.x;

    // stage tree + indexes into smem
    const float4* tin = (const float4*)(trees + (size_t)b * 16384);
    float4* s0v = (float4*)S0;
    for (int i = tid; i < 4096; i += TPB) s0v[i] = tin[i];
    const int* ip = indexes + (size_t)b * 381;
    for (int i = tid; i < 381; i += TPB) IDX[i] = ip[i];
    __syncthreads();

    conv_store<128, 256, false>(S0, S1, g_Wt1, b1, G0, G1, IDX, RED, STAT,
                                tid, w, lane, 0.f, 1.f);
    float m1 = STAT[0], i1 = STAT[1];
    conv_store<256, 128, true >(S1, S0, g_Wt2, b2, G0, G1, IDX, RED, STAT,
                                tid, w, lane, m1, i1);
    float m2 = STAT[0], i2 = STAT[1];
    conv_pool <128, 64, true>(S0, g_Wt3, b3, G0, G1, IDX, RED, POOL, STAT,
                              tid, w, lane, m2, i2);

    // head on warp 0: h = leaky(pooled_ln @ W4^T + b4); out = h @ W5^T + b5
    if (w == 0) {
        float mean = STAT[0], inv = STAT[1];
        float hv = b4[lane];
#pragma unroll 8
        for (int c = 0; c < 64; c++)
            hv += (POOL[c] - mean) * inv * W4[lane * 64 + c];
        hv = hv > 0.f ? hv : 0.01f * hv;
        float val = wredsum(hv * W5[lane]);
        if (lane == 0) out[b] = val + b5[0];
    }
}

extern "C" void kernel_launch(void* const* d_in, const int* in_sizes, int n_in,
                              void* d_out, int out_size) {
    const float* trees = nullptr; const int* indexes = nullptr;
    const float *W1 = nullptr, *b1 = nullptr, *W2 = nullptr, *b2 = nullptr;
    const float *W3 = nullptr, *b3 = nullptr, *W4 = nullptr, *b4 = nullptr;
    const float *W5 = nullptr, *b5 = nullptr;

    for (int i = 0; i < n_in; i++) {
        int s = in_sizes[i];
        const void* p = d_in[i];
        switch (s) {
            case 33554432: trees   = (const float*)p; break;
            case 780288:   indexes = (const int*)p;   break;
            case 98304:    if (!W1) W1 = (const float*)p; else W2 = (const float*)p; break;
            case 256:      b1 = (const float*)p; break;
            case 128:      b2 = (const float*)p; break;
            case 24576:    W3 = (const float*)p; break;
            case 64:       b3 = (const float*)p; break;
            case 2048:     W4 = (const float*)p; break;
            case 32:       if (!b4) b4 = (const float*)p; else W5 = (const float*)p; break;
            case 1:        b5 = (const float*)p; break;
            default: break;
        }
    }

    prep1<<<(128 * 3 * 256 + 255) / 256, 256>>>(W1);
    prep2<<<(256 * 3 * 128 + 255) / 256, 256>>>(W2);
    prep3<<<(128 * 3 * 64  + 255) / 256, 256>>>(W3);

    cudaFuncSetAttribute(bao_kernel, cudaFuncAttributeMaxDynamicSharedMemorySize, SMEM_BYTES);
    bao_kernel<<<2048, TPB, SMEM_BYTES>>>(trees, indexes, b1, b2, b3, W4, b4, W5, b5,
                                          (float*)d_out);
}